// round 13
// baseline (speedup 1.0000x reference)
#include <cuda_runtime.h>
#include <math.h>

constexpr int NN = 50000;   // nodes
constexpr int HH = 16;      // hidden
constexpr int RR = 32;      // relations
constexpr int CC = 8;       // classes
constexpr int EMAX = 1600000;
constexpr int NB = (NN + 255) / 256;   // 196 scan blocks

// Scratch (device globals; zero-initialized at load, invariants restored per call)
__device__ float    g_x[NN * HH];      // layer-1 node features
__device__ unsigned g_pk32[EMAX];      // d-sorted packed edges: s | r<<16
__device__ int      g_dhist[NN];       // per-dst histogram (zero on entry; re-zeroed in scanC)
__device__ int      g_start[NN + 1];   // segment starts (exclusive scan)
__device__ int      g_cursor[NN];      // scatter cursors (recomputed every call)
__device__ int      g_bsum[256];       // block sums for scan
__device__ int      g_boff[256];       // block offsets for scan

// ---------------------------------------------------------------------------
// 0) per-destination histogram
__global__ void k_hist(const int* __restrict__ dstv, int E) {
    int e = blockIdx.x * blockDim.x + threadIdx.x;
    if (e < E) atomicAdd(&g_dhist[dstv[e]], 1);
}

// 1a) block sums
__global__ void k_scanA() {
    __shared__ int sh[256];
    int t = threadIdx.x;
    int i = blockIdx.x * 256 + t;
    sh[t] = (i < NN) ? g_dhist[i] : 0;
    __syncthreads();
    for (int o = 128; o > 0; o >>= 1) {
        if (t < o) sh[t] += sh[t + o];
        __syncthreads();
    }
    if (t == 0) g_bsum[blockIdx.x] = sh[0];
}

// 1b) exclusive scan of block sums (single block)
__global__ void k_scanB() {
    __shared__ int sh[256];
    int t = threadIdx.x;
    int v = (t < NB) ? g_bsum[t] : 0;
    sh[t] = v;
    __syncthreads();
    for (int o = 1; o < 256; o <<= 1) {
        int a = (t >= o) ? sh[t - o] : 0;
        __syncthreads();
        sh[t] += a;
        __syncthreads();
    }
    if (t < NB) g_boff[t] = sh[t] - v;   // exclusive
}

// 1c) per-block exclusive scan + offset -> start/cursor; re-zero dhist for next call
__global__ void k_scanC(int E) {
    __shared__ int sh[256];
    int t = threadIdx.x;
    int i = blockIdx.x * 256 + t;
    int v = (i < NN) ? g_dhist[i] : 0;
    sh[t] = v;
    __syncthreads();
    for (int o = 1; o < 256; o <<= 1) {
        int a = (t >= o) ? sh[t - o] : 0;
        __syncthreads();
        sh[t] += a;
        __syncthreads();
    }
    int st = sh[t] - v + g_boff[blockIdx.x];   // exclusive prefix
    if (i <= NN) g_start[i] = st;              // i==NN gets E
    if (i < NN) { g_cursor[i] = st; g_dhist[i] = 0; }
}

// 2) scatter edges into d-sorted packed array (4 bytes/edge: s | r<<16)
__global__ void k_scatter(const int* __restrict__ et, const int* __restrict__ srcv,
                          const int* __restrict__ dstv, int E) {
    int e = blockIdx.x * blockDim.x + threadIdx.x;
    if (e >= E) return;
    int d = dstv[e];
    int pos = atomicAdd(&g_cursor[d], 1);
    g_pk32[pos] = (unsigned)srcv[e] | ((unsigned)et[e] << 16);
}

// 3) fused layer 1: one warp per node d.
//    counts per relation locally (R=32=warp), accumulates w1 rows in registers,
//    stores x[d] = relu(sum + root1 + b1). No atomics, no cnt table, no init.
__global__ void __launch_bounds__(256) k_l1(const float* __restrict__ w1,
                                            const float* __restrict__ root1,
                                            const float* __restrict__ b1) {
    __shared__ int scnt[8][RR];
    int t = threadIdx.x, wid = t >> 5, lane = t & 31, q = lane & 3;
    int d = (blockIdx.x * 256 + t) >> 5;      // grid sized to exactly NN warps
    int start = g_start[d], end = g_start[d + 1];

    scnt[wid][lane] = 0;
    __syncwarp();
    for (int i = start + lane; i < end; i += 32)
        atomicAdd(&scnt[wid][g_pk32[i] >> 16], 1);
    __syncwarp();
    int c = scnt[wid][lane];
    float inv_lane = __fdividef(1.0f, (float)(c > 0 ? c : 1));

    float4 acc = make_float4(0.f, 0.f, 0.f, 0.f);
    for (int base = start; base < end; base += 8) {
        int ei = base + (lane >> 2);
        bool v = ei < end;
        unsigned pk = v ? __ldg(&g_pk32[ei]) : 0u;
        int s = (int)(pk & 0xFFFFu), r = (int)(pk >> 16);
        float inv = __shfl_sync(0xffffffffu, inv_lane, r);
        if (v) {
            float4 w = __ldg(((const float4*)(w1 + ((long)(r * NN + s) << 4))) + q);
            acc.x += inv * w.x; acc.y += inv * w.y;
            acc.z += inv * w.z; acc.w += inv * w.w;
        }
    }
    // reduce across the 8 edge slots sharing this q (xor 4, 8, 16)
#pragma unroll
    for (int o = 4; o < 32; o <<= 1) {
        acc.x += __shfl_xor_sync(0xffffffffu, acc.x, o);
        acc.y += __shfl_xor_sync(0xffffffffu, acc.y, o);
        acc.z += __shfl_xor_sync(0xffffffffu, acc.z, o);
        acc.w += __shfl_xor_sync(0xffffffffu, acc.w, o);
    }
    if (lane < 4) {
        float4 rt = __ldg(((const float4*)(root1 + d * HH)) + lane);
        float4 bb = __ldg(((const float4*)b1) + lane);
        float4 o;
        o.x = fmaxf(acc.x + rt.x + bb.x, 0.f);
        o.y = fmaxf(acc.y + rt.y + bb.y, 0.f);
        o.z = fmaxf(acc.z + rt.z + bb.z, 0.f);
        o.w = fmaxf(acc.w + rt.w + bb.w, 0.f);
        *(((float4*)(g_x + d * HH)) + lane) = o;
    }
}

// 4) fused layer 2: one warp per node d (persistent grid).
//    out[d] = log_softmax( sum_e inv[r]*(x[s] @ w2[r]) + x[d] @ root2 + b2 )
__global__ void __launch_bounds__(256) k_l2(const float* __restrict__ w2,
                                            const float* __restrict__ root2,
                                            const float* __restrict__ b2,
                                            float* __restrict__ out) {
    __shared__ float s_w2[RR * HH * CC];   // 16 KB
    __shared__ float s_r2[HH * CC];
    __shared__ float s_b2[CC];
    __shared__ int   scnt[8][RR];
    int t = threadIdx.x, wid = t >> 5, lane = t & 31, q = lane & 3;
    for (int i = t; i < RR * HH * CC; i += 256) s_w2[i] = w2[i];
    for (int i = t; i < HH * CC; i += 256) s_r2[i] = root2[i];
    if (t < CC) s_b2[t] = b2[t];
    __syncthreads();

    int wglob = (blockIdx.x * 256 + t) >> 5;
    int wtot  = (gridDim.x * 256) >> 5;

    for (int d = wglob; d < NN; d += wtot) {
        int start = g_start[d], end = g_start[d + 1];

        scnt[wid][lane] = 0;
        __syncwarp();
        for (int i = start + lane; i < end; i += 32)
            atomicAdd(&scnt[wid][g_pk32[i] >> 16], 1);
        __syncwarp();
        int c = scnt[wid][lane];
        float inv_lane = __fdividef(1.0f, (float)(c > 0 ? c : 1));

        float y[CC] = {0.f, 0.f, 0.f, 0.f, 0.f, 0.f, 0.f, 0.f};
        for (int base = start; base < end; base += 8) {
            int ei = base + (lane >> 2);
            bool v = ei < end;
            unsigned pk = v ? __ldg(&g_pk32[ei]) : 0u;
            int s = (int)(pk & 0xFFFFu), r = (int)(pk >> 16);
            float inv = __shfl_sync(0xffffffffu, inv_lane, r);
            if (v) {
                float4 xq = __ldg(((const float4*)(g_x + s * HH)) + q);
                float xv[4] = {xq.x * inv, xq.y * inv, xq.z * inv, xq.w * inv};
                const float* wr = s_w2 + r * HH * CC + q * 4 * CC;
#pragma unroll
                for (int j = 0; j < 4; j++) {
                    float va = xv[j];
                    const float* row = wr + j * CC;
                    y[0] += va * row[0]; y[1] += va * row[1];
                    y[2] += va * row[2]; y[3] += va * row[3];
                    y[4] += va * row[4]; y[5] += va * row[5];
                    y[6] += va * row[6]; y[7] += va * row[7];
                }
            }
        }
        // full warp reduction of y
#pragma unroll
        for (int o = 1; o < 32; o <<= 1) {
#pragma unroll
            for (int cc = 0; cc < CC; cc++)
                y[cc] += __shfl_xor_sync(0xffffffffu, y[cc], o);
        }

        if (lane == 0) {
#pragma unroll
            for (int h = 0; h < HH; h++) {
                float xv = g_x[d * HH + h];
#pragma unroll
                for (int cc = 0; cc < CC; cc++) y[cc] += xv * s_r2[h * CC + cc];
            }
#pragma unroll
            for (int cc = 0; cc < CC; cc++) y[cc] += s_b2[cc];

            float m = y[0];
#pragma unroll
            for (int cc = 1; cc < CC; cc++) m = fmaxf(m, y[cc]);
            float sum = 0.f;
#pragma unroll
            for (int cc = 0; cc < CC; cc++) sum += __expf(y[cc] - m);
            float l = m + logf(sum);
            float4 o0 = make_float4(y[0] - l, y[1] - l, y[2] - l, y[3] - l);
            float4 o1 = make_float4(y[4] - l, y[5] - l, y[6] - l, y[7] - l);
            *(float4*)(out + d * CC) = o0;
            *(float4*)(out + d * CC + 4) = o1;
        }
    }
}

// ---------------------------------------------------------------------------
extern "C" void kernel_launch(void* const* d_in, const int* in_sizes, int n_in,
                              void* d_out, int out_size) {
    const int*   ei    = (const int*)d_in[0];     // [2, E]
    const int*   et    = (const int*)d_in[1];     // [E]
    const float* w1    = (const float*)d_in[2];   // [R, N, H]
    const float* root1 = (const float*)d_in[3];   // [N, H]
    const float* b1    = (const float*)d_in[4];   // [H]
    const float* w2    = (const float*)d_in[5];   // [R, H, C]
    const float* root2 = (const float*)d_in[6];   // [H, C]
    const float* b2    = (const float*)d_in[7];   // [C]
    float* out = (float*)d_out;

    const int E = in_sizes[0] / 2;
    const int* srcv = ei;
    const int* dstv = ei + E;

    const int T = 256;
    k_hist    <<<(E + T - 1) / T, T>>> (dstv, E);
    k_scanA   <<<NB, T>>> ();
    k_scanB   <<<1, T>>> ();
    k_scanC   <<<NB, T>>> (E);
    k_scatter <<<(E + T - 1) / T, T>>> (et, srcv, dstv, E);
    k_l1      <<<(NN * 32) / T, T>>> (w1, root1, b1);   // exactly NN warps
    k_l2      <<<1184, T>>> (w2, root2, b2, out);
    k_fin_unused:;
}

// round 14
// speedup vs baseline: 2.0517x; 2.0517x over previous
#include <cuda_runtime.h>
#include <math.h>

constexpr int NN = 50000;   // nodes
constexpr int HH = 16;      // hidden
constexpr int RR = 32;      // relations
constexpr int CC = 8;       // classes
constexpr int RN = RR * NN; // segments
constexpr int EMAX = 1600000;

// Scratch (device globals: no allocation allowed).
// g_cnt invariant: zero at kernel_launch entry (zero-init at load; re-zeroed by k_l1).
__device__ int                g_cnt[RN];     // edge counts per (rel,dst)
__device__ float              g_x[NN * HH];  // layer-1 node features
__device__ __align__(16) unsigned long long g_pk[EMAX + 2]; // s | d<<16 | r<<32 | c<<40
__device__ int                g_hist[RR];    // relation histogram (re-zeroed by k_scan)
__device__ int                g_cursor[RR];  // scatter cursors

// ---------------------------------------------------------------------------
// 0) zero g_x/out + relation histogram + (rel,dst) segment counts
__global__ void k_init_hist(const int* __restrict__ et, const int* __restrict__ dstv,
                            float* __restrict__ out, int E) {
    __shared__ int sh[RR];
    int t = threadIdx.x;
    if (t < RR) sh[t] = 0;
    __syncthreads();
    int i = blockIdx.x * blockDim.x + t;
    if (i < NN * HH) g_x[i] = 0.0f;
    if (i < NN * CC) out[i] = 0.0f;
    if (i < E) {
        int r = et[i];
        atomicAdd(&sh[r], 1);
        atomicAdd(&g_cnt[r * NN + dstv[i]], 1);
    }
    __syncthreads();
    if (t < RR) {
        int v = sh[t];
        if (v) atomicAdd(&g_hist[t], v);
    }
}

// 1) exclusive scan of 32-bin histogram -> cursors; re-zero g_hist for next replay
__global__ void k_scan() {
    __shared__ int s[RR];
    int t = threadIdx.x;
    s[t] = g_hist[t];
    __syncthreads();
    if (t == 0) {
        int acc = 0;
        for (int i = 0; i < RR; i++) { int v = s[i]; s[i] = acc; acc += v; }
    }
    __syncthreads();
    g_cursor[t] = s[t];
    g_hist[t] = 0;
}

// 2) scatter edges into relation-sorted packed array (warp-aggregated ranks);
//    bakes the (now-final) segment count into the edge word.
__global__ void k_scatter(const int* __restrict__ et, const int* __restrict__ srcv,
                          const int* __restrict__ dstv, int E) {
    __shared__ int sh[RR];
    __shared__ int sbase[RR];
    int t = threadIdx.x;
    if (t < RR) sh[t] = 0;
    __syncthreads();

    int e = blockIdx.x * blockDim.x + t;
    bool ok = e < E;
    int r = ok ? et[e] : RR;
    int s = 0, d = 0;
    if (ok) { s = srcv[e]; d = dstv[e]; }

    unsigned m = __match_any_sync(0xffffffffu, r);
    int lane = t & 31;
    int leader = __ffs(m) - 1;
    int pre = __popc(m & ((1u << lane) - 1));
    int base = 0;
    if (lane == leader && r < RR) base = atomicAdd(&sh[r], __popc(m));
    base = __shfl_sync(0xffffffffu, base, leader);
    int rank = base + pre;

    __syncthreads();
    if (t < RR) sbase[t] = sh[t] ? atomicAdd(&g_cursor[t], sh[t]) : 0;
    __syncthreads();

    if (ok) {
        unsigned c = (unsigned)__ldg(&g_cnt[r * NN + d]);   // final count
        g_pk[sbase[r] + rank] = (unsigned long long)(unsigned)s
                              | ((unsigned long long)(unsigned)d << 16)
                              | ((unsigned long long)(unsigned)r << 32)
                              | ((unsigned long long)c << 40);
    }
}

// 3) layer-1 scatter: x[d] += (1/c) * w1[r,s]
//    2 edges per 4-lane group (ulonglong2); count decoded from edge word.
//    Also re-zeroes g_cnt (coalesced; restores the replay invariant).
__global__ void k_l1(const float* __restrict__ w1, int E) {
    int idx = blockIdx.x * blockDim.x + threadIdx.x;
    if (idx < RN) g_cnt[idx] = 0;                 // fold re-zeroing into this pass

    int g = idx >> 2, q = idx & 3;
    int e0 = 2 * g;
    if (e0 >= E) return;
    bool ok1 = (e0 + 1) < E;

    ulonglong2 pv = __ldg(((const ulonglong2*)g_pk) + g);
    unsigned long long p0 = pv.x, p1 = pv.y;

    int s0 = (int)(p0 & 0xFFFFu), d0 = (int)((p0 >> 16) & 0xFFFFu);
    int r0 = (int)((p0 >> 32) & 0xFFu), c0 = (int)((p0 >> 40) & 0xFFFFu);
    int s1 = (int)(p1 & 0xFFFFu), d1 = (int)((p1 >> 16) & 0xFFFFu);
    int r1 = (int)((p1 >> 32) & 0xFFu), c1 = (int)((p1 >> 40) & 0xFFFFu);

    const float4 w0 = __ldg(((const float4*)(w1 + ((long)(r0 * NN + s0) << 4))) + q);
    float4 w1v = make_float4(0.f, 0.f, 0.f, 0.f);
    if (ok1) w1v = __ldg(((const float4*)(w1 + ((long)(r1 * NN + s1) << 4))) + q);

    float i0 = __fdividef(1.0f, (float)c0);
    float i1 = ok1 ? __fdividef(1.0f, (float)c1) : 0.0f;

    float* pd0 = &g_x[d0 * HH + q * 4];
    asm volatile("red.global.add.v4.f32 [%0], {%1,%2,%3,%4};"
                 :: "l"(pd0), "f"(w0.x * i0), "f"(w0.y * i0),
                    "f"(w0.z * i0), "f"(w0.w * i0) : "memory");
    if (ok1) {
        float* pd1 = &g_x[d1 * HH + q * 4];
        asm volatile("red.global.add.v4.f32 [%0], {%1,%2,%3,%4};"
                     :: "l"(pd1), "f"(w1v.x * i1), "f"(w1v.y * i1),
                        "f"(w1v.z * i1), "f"(w1v.w * i1) : "memory");
    }
}

// 4) x = relu(x + root1 + b1)  (float4)
__global__ void k_relu(const float4* __restrict__ root1, const float* __restrict__ b1) {
    int i = blockIdx.x * blockDim.x + threadIdx.x;
    if (i >= NN * HH / 4) return;
    float4 v = ((float4*)g_x)[i];
    float4 rr = __ldg(root1 + i);
    int q = (i & 3) * 4;
    v.x += rr.x + b1[q];
    v.y += rr.y + b1[q + 1];
    v.z += rr.z + b1[q + 2];
    v.w += rr.w + b1[q + 3];
    v.x = fmaxf(v.x, 0.f); v.y = fmaxf(v.y, 0.f);
    v.z = fmaxf(v.z, 0.f); v.w = fmaxf(v.w, 0.f);
    ((float4*)g_x)[i] = v;
}

// 5) layer-2 scatter: out[d] += (1/c) * (x[s] @ w2[r])
//    1 thread/edge, grid-stride; r-sorted -> warp-uniform r -> broadcast smem reads
__global__ void __launch_bounds__(256) k_l2(const float* __restrict__ w2,
                                            float* __restrict__ out, int E) {
    __shared__ float s_w2[RR * HH * CC];   // 16 KB
    for (int i = threadIdx.x; i < RR * HH * CC; i += blockDim.x) s_w2[i] = w2[i];
    __syncthreads();

    int stride = gridDim.x * blockDim.x;
    for (int e = blockIdx.x * blockDim.x + threadIdx.x; e < E; e += stride) {
        unsigned long long p = __ldg(&g_pk[e]);
        int s = (int)(p & 0xFFFFu);
        int d = (int)((p >> 16) & 0xFFFFu);
        int r = (int)((p >> 32) & 0xFFu);
        int c0 = (int)((p >> 40) & 0xFFFFu);
        float inv = __fdividef(1.0f, (float)c0);

        const float4* xr = (const float4*)(g_x + s * HH);
        float4 x0 = __ldg(xr), x1 = __ldg(xr + 1), x2 = __ldg(xr + 2), x3 = __ldg(xr + 3);
        float xs[16] = {x0.x, x0.y, x0.z, x0.w, x1.x, x1.y, x1.z, x1.w,
                        x2.x, x2.y, x2.z, x2.w, x3.x, x3.y, x3.z, x3.w};

        const float* wr = s_w2 + r * HH * CC;
        float y[CC] = {0.f, 0.f, 0.f, 0.f, 0.f, 0.f, 0.f, 0.f};
#pragma unroll
        for (int h = 0; h < HH; h++) {
            float xv = xs[h];
#pragma unroll
            for (int c = 0; c < CC; c++) y[c] += xv * wr[h * CC + c];
        }
        float* pd = out + d * CC;
        asm volatile("red.global.add.v4.f32 [%0], {%1,%2,%3,%4};"
                     :: "l"(pd), "f"(y[0] * inv), "f"(y[1] * inv),
                        "f"(y[2] * inv), "f"(y[3] * inv) : "memory");
        asm volatile("red.global.add.v4.f32 [%0], {%1,%2,%3,%4};"
                     :: "l"(pd + 4), "f"(y[4] * inv), "f"(y[5] * inv),
                        "f"(y[6] * inv), "f"(y[7] * inv) : "memory");
    }
}

// 6) finalize: out = log_softmax(out + x @ root2 + b2)
__global__ void k_fin(const float* __restrict__ root2, const float* __restrict__ b2,
                      float* __restrict__ out) {
    __shared__ float s_r2[HH * CC];
    __shared__ float s_b2[CC];
    for (int i = threadIdx.x; i < HH * CC; i += blockDim.x) s_r2[i] = root2[i];
    if (threadIdx.x < CC) s_b2[threadIdx.x] = b2[threadIdx.x];
    __syncthreads();

    int n = blockIdx.x * blockDim.x + threadIdx.x;
    if (n >= NN) return;

    float y[CC];
    float4 a0 = *(const float4*)(out + n * CC);
    float4 a1 = *(const float4*)(out + n * CC + 4);
    y[0] = a0.x; y[1] = a0.y; y[2] = a0.z; y[3] = a0.w;
    y[4] = a1.x; y[5] = a1.y; y[6] = a1.z; y[7] = a1.w;

#pragma unroll
    for (int h = 0; h < HH; h++) {
        float xv = g_x[n * HH + h];
#pragma unroll
        for (int c = 0; c < CC; c++) y[c] += xv * s_r2[h * CC + c];
    }
#pragma unroll
    for (int c = 0; c < CC; c++) y[c] += s_b2[c];

    float m = y[0];
#pragma unroll
    for (int c = 1; c < CC; c++) m = fmaxf(m, y[c]);
    float sum = 0.0f;
#pragma unroll
    for (int c = 0; c < CC; c++) sum += __expf(y[c] - m);
    float l = m + logf(sum);
#pragma unroll
    for (int c = 0; c < CC; c++) out[n * CC + c] = y[c] - l;
}

// ---------------------------------------------------------------------------
extern "C" void kernel_launch(void* const* d_in, const int* in_sizes, int n_in,
                              void* d_out, int out_size) {
    const int*   ei    = (const int*)d_in[0];     // [2, E]
    const int*   et    = (const int*)d_in[1];     // [E]
    const float* w1    = (const float*)d_in[2];   // [R, N, H]
    const float* root1 = (const float*)d_in[3];   // [N, H]
    const float* b1    = (const float*)d_in[4];   // [H]
    const float* w2    = (const float*)d_in[5];   // [R, H, C]
    const float* root2 = (const float*)d_in[6];   // [H, C]
    const float* b2    = (const float*)d_in[7];   // [C]
    float* out = (float*)d_out;

    const int E = in_sizes[0] / 2;
    const int* srcv = ei;
    const int* dstv = ei + E;

    const int T = 256;
    k_init_hist <<<(E + T - 1) / T, T>>> (et, dstv, out, E);
    k_scan      <<<1, RR>>> ();
    k_scatter   <<<(E + T - 1) / T, T>>> (et, srcv, dstv, E);
    int pairs = (E + 1) / 2;
    int l1threads = 4 * pairs > RN ? 4 * pairs : RN;
    k_l1        <<<(l1threads + T - 1) / T, T>>> (w1, E);
    k_relu      <<<(NN * HH / 4 + T - 1) / T, T>>> ((const float4*)root1, b1);
    k_l2        <<<1184, T>>> (w2, out, E);
    k_fin       <<<(NN + T - 1) / T, T>>> (root2, b2, out);
}

// round 15
// speedup vs baseline: 2.2893x; 1.1158x over previous
#include <cuda_runtime.h>
#include <cuda_fp16.h>
#include <math.h>

constexpr int NN = 50000;   // nodes
constexpr int HH = 16;      // hidden
constexpr int RR = 32;      // relations
constexpr int CC = 8;       // classes
constexpr int RN = RR * NN; // segments
constexpr int EMAX = 1600000;

// Scratch (device globals: no allocation allowed).
// g_cnt invariant: zero at kernel_launch entry (zero-init at load; re-zeroed by k_l1).
__device__ int                g_cnt[RN];     // edge counts per (rel,dst)
__device__ float              g_x[NN * HH];  // layer-1 node features (fp32)
__device__ __align__(16) __half g_xh[NN * HH]; // fp16 copy for layer-2 gather
__device__ __align__(16) unsigned long long g_pk[EMAX + 2]; // s | d<<16 | r<<32 | c<<40
__device__ int                g_hist[RR];    // relation histogram (re-zeroed by k_scan)
__device__ int                g_cursor[RR];  // scatter cursors

// ---------------------------------------------------------------------------
// 0) zero g_x/out + relation histogram + (rel,dst) segment counts
__global__ void k_init_hist(const int* __restrict__ et, const int* __restrict__ dstv,
                            float* __restrict__ out, int E) {
    __shared__ int sh[RR];
    int t = threadIdx.x;
    if (t < RR) sh[t] = 0;
    __syncthreads();
    int i = blockIdx.x * blockDim.x + t;
    if (i < NN * HH) g_x[i] = 0.0f;
    if (i < NN * CC) out[i] = 0.0f;
    if (i < E) {
        int r = et[i];
        atomicAdd(&sh[r], 1);
        atomicAdd(&g_cnt[r * NN + dstv[i]], 1);
    }
    __syncthreads();
    if (t < RR) {
        int v = sh[t];
        if (v) atomicAdd(&g_hist[t], v);
    }
}

// 1) exclusive scan of 32-bin histogram -> cursors; re-zero g_hist for next replay
__global__ void k_scan() {
    __shared__ int s[RR];
    int t = threadIdx.x;
    s[t] = g_hist[t];
    __syncthreads();
    if (t == 0) {
        int acc = 0;
        for (int i = 0; i < RR; i++) { int v = s[i]; s[i] = acc; acc += v; }
    }
    __syncthreads();
    g_cursor[t] = s[t];
    g_hist[t] = 0;
}

// 2) scatter edges into relation-sorted packed array (warp-aggregated ranks);
//    bakes the (final) segment count into the edge word.
__global__ void k_scatter(const int* __restrict__ et, const int* __restrict__ srcv,
                          const int* __restrict__ dstv, int E) {
    __shared__ int sh[RR];
    __shared__ int sbase[RR];
    int t = threadIdx.x;
    if (t < RR) sh[t] = 0;
    __syncthreads();

    int e = blockIdx.x * blockDim.x + t;
    bool ok = e < E;
    int r = ok ? et[e] : RR;
    int s = 0, d = 0;
    if (ok) { s = srcv[e]; d = dstv[e]; }

    unsigned m = __match_any_sync(0xffffffffu, r);
    int lane = t & 31;
    int leader = __ffs(m) - 1;
    int pre = __popc(m & ((1u << lane) - 1));
    int base = 0;
    if (lane == leader && r < RR) base = atomicAdd(&sh[r], __popc(m));
    base = __shfl_sync(0xffffffffu, base, leader);
    int rank = base + pre;

    __syncthreads();
    if (t < RR) sbase[t] = sh[t] ? atomicAdd(&g_cursor[t], sh[t]) : 0;
    __syncthreads();

    if (ok) {
        unsigned c = (unsigned)__ldg(&g_cnt[r * NN + d]);   // final count
        g_pk[sbase[r] + rank] = (unsigned long long)(unsigned)s
                              | ((unsigned long long)(unsigned)d << 16)
                              | ((unsigned long long)(unsigned)r << 32)
                              | ((unsigned long long)c << 40);
    }
}

// 3) layer-1 scatter: x[d] += (1/c) * w1[r,s]
//    2 edges per 4-lane group (ulonglong2); count decoded from edge word.
//    Also re-zeroes g_cnt (coalesced; restores the replay invariant).
__global__ void k_l1(const float* __restrict__ w1, int E) {
    int idx = blockIdx.x * blockDim.x + threadIdx.x;
    if (idx < RN) g_cnt[idx] = 0;                 // fold re-zeroing into this pass

    int g = idx >> 2, q = idx & 3;
    int e0 = 2 * g;
    if (e0 >= E) return;
    bool ok1 = (e0 + 1) < E;

    ulonglong2 pv = __ldg(((const ulonglong2*)g_pk) + g);
    unsigned long long p0 = pv.x, p1 = pv.y;

    int s0 = (int)(p0 & 0xFFFFu), d0 = (int)((p0 >> 16) & 0xFFFFu);
    int r0 = (int)((p0 >> 32) & 0xFFu), c0 = (int)((p0 >> 40) & 0xFFFFu);
    int s1 = (int)(p1 & 0xFFFFu), d1 = (int)((p1 >> 16) & 0xFFFFu);
    int r1 = (int)((p1 >> 32) & 0xFFu), c1 = (int)((p1 >> 40) & 0xFFFFu);

    const float4 w0 = __ldg(((const float4*)(w1 + ((long)(r0 * NN + s0) << 4))) + q);
    float4 w1v = make_float4(0.f, 0.f, 0.f, 0.f);
    if (ok1) w1v = __ldg(((const float4*)(w1 + ((long)(r1 * NN + s1) << 4))) + q);

    float i0 = __fdividef(1.0f, (float)c0);
    float i1 = ok1 ? __fdividef(1.0f, (float)c1) : 0.0f;

    float* pd0 = &g_x[d0 * HH + q * 4];
    asm volatile("red.global.add.v4.f32 [%0], {%1,%2,%3,%4};"
                 :: "l"(pd0), "f"(w0.x * i0), "f"(w0.y * i0),
                    "f"(w0.z * i0), "f"(w0.w * i0) : "memory");
    if (ok1) {
        float* pd1 = &g_x[d1 * HH + q * 4];
        asm volatile("red.global.add.v4.f32 [%0], {%1,%2,%3,%4};"
                     :: "l"(pd1), "f"(w1v.x * i1), "f"(w1v.y * i1),
                        "f"(w1v.z * i1), "f"(w1v.w * i1) : "memory");
    }
}

// 4) x = relu(x + root1 + b1)  (float4); also writes fp16 copy for l2 gather
__global__ void k_relu(const float4* __restrict__ root1, const float* __restrict__ b1) {
    int i = blockIdx.x * blockDim.x + threadIdx.x;
    if (i >= NN * HH / 4) return;
    float4 v = ((float4*)g_x)[i];
    float4 rr = __ldg(root1 + i);
    int q = (i & 3) * 4;
    v.x += rr.x + b1[q];
    v.y += rr.y + b1[q + 1];
    v.z += rr.z + b1[q + 2];
    v.w += rr.w + b1[q + 3];
    v.x = fmaxf(v.x, 0.f); v.y = fmaxf(v.y, 0.f);
    v.z = fmaxf(v.z, 0.f); v.w = fmaxf(v.w, 0.f);
    ((float4*)g_x)[i] = v;
    __half2 h0 = __floats2half2_rn(v.x, v.y);
    __half2 h1 = __floats2half2_rn(v.z, v.w);
    ((__half2*)g_xh)[2 * i]     = h0;
    ((__half2*)g_xh)[2 * i + 1] = h1;
}

// 5) layer-2 scatter: out[d] += (1/c) * (x[s] @ w2[r])
//    1 thread/edge, grid-stride; fp16 x gather (2 LDG.128/edge); fp32 math.
__global__ void __launch_bounds__(256) k_l2(const float* __restrict__ w2,
                                            float* __restrict__ out, int E) {
    __shared__ float s_w2[RR * HH * CC];   // 16 KB
    for (int i = threadIdx.x; i < RR * HH * CC; i += blockDim.x) s_w2[i] = w2[i];
    __syncthreads();

    int stride = gridDim.x * blockDim.x;
    for (int e = blockIdx.x * blockDim.x + threadIdx.x; e < E; e += stride) {
        unsigned long long p = __ldg(&g_pk[e]);
        int s = (int)(p & 0xFFFFu);
        int d = (int)((p >> 16) & 0xFFFFu);
        int r = (int)((p >> 32) & 0xFFu);
        int c0 = (int)((p >> 40) & 0xFFFFu);
        float inv = __fdividef(1.0f, (float)c0);

        const uint4* xr = (const uint4*)(g_xh + s * HH);
        uint4 hA = __ldg(xr);          // halves 0..7
        uint4 hB = __ldg(xr + 1);      // halves 8..15
        float xs[16];
        {
            float2 f;
            f = __half22float2(*(const __half2*)&hA.x); xs[0] = f.x; xs[1] = f.y;
            f = __half22float2(*(const __half2*)&hA.y); xs[2] = f.x; xs[3] = f.y;
            f = __half22float2(*(const __half2*)&hA.z); xs[4] = f.x; xs[5] = f.y;
            f = __half22float2(*(const __half2*)&hA.w); xs[6] = f.x; xs[7] = f.y;
            f = __half22float2(*(const __half2*)&hB.x); xs[8] = f.x; xs[9] = f.y;
            f = __half22float2(*(const __half2*)&hB.y); xs[10] = f.x; xs[11] = f.y;
            f = __half22float2(*(const __half2*)&hB.z); xs[12] = f.x; xs[13] = f.y;
            f = __half22float2(*(const __half2*)&hB.w); xs[14] = f.x; xs[15] = f.y;
        }

        const float* wr = s_w2 + r * HH * CC;
        float y[CC] = {0.f, 0.f, 0.f, 0.f, 0.f, 0.f, 0.f, 0.f};
#pragma unroll
        for (int h = 0; h < HH; h++) {
            float xv = xs[h];
#pragma unroll
            for (int c = 0; c < CC; c++) y[c] += xv * wr[h * CC + c];
        }
        float* pd = out + d * CC;
        asm volatile("red.global.add.v4.f32 [%0], {%1,%2,%3,%4};"
                     :: "l"(pd), "f"(y[0] * inv), "f"(y[1] * inv),
                        "f"(y[2] * inv), "f"(y[3] * inv) : "memory");
        asm volatile("red.global.add.v4.f32 [%0], {%1,%2,%3,%4};"
                     :: "l"(pd + 4), "f"(y[4] * inv), "f"(y[5] * inv),
                        "f"(y[6] * inv), "f"(y[7] * inv) : "memory");
    }
}

// 6) finalize: out = log_softmax(out + x @ root2 + b2)   (fp32 x)
__global__ void k_fin(const float* __restrict__ root2, const float* __restrict__ b2,
                      float* __restrict__ out) {
    __shared__ float s_r2[HH * CC];
    __shared__ float s_b2[CC];
    for (int i = threadIdx.x; i < HH * CC; i += blockDim.x) s_r2[i] = root2[i];
    if (threadIdx.x < CC) s_b2[threadIdx.x] = b2[threadIdx.x];
    __syncthreads();

    int n = blockIdx.x * blockDim.x + threadIdx.x;
    if (n >= NN) return;

    float y[CC];
    float4 a0 = *(const float4*)(out + n * CC);
    float4 a1 = *(const float4*)(out + n * CC + 4);
    y[0] = a0.x; y[1] = a0.y; y[2] = a0.z; y[3] = a0.w;
    y[4] = a1.x; y[5] = a1.y; y[6] = a1.z; y[7] = a1.w;

#pragma unroll
    for (int h = 0; h < HH; h++) {
        float xv = g_x[n * HH + h];
#pragma unroll
        for (int c = 0; c < CC; c++) y[c] += xv * s_r2[h * CC + c];
    }
#pragma unroll
    for (int c = 0; c < CC; c++) y[c] += s_b2[c];

    float m = y[0];
#pragma unroll
    for (int c = 1; c < CC; c++) m = fmaxf(m, y[c]);
    float sum = 0.0f;
#pragma unroll
    for (int c = 0; c < CC; c++) sum += __expf(y[c] - m);
    float l = m + logf(sum);
#pragma unroll
    for (int c = 0; c < CC; c++) out[n * CC + c] = y[c] - l;
}

// ---------------------------------------------------------------------------
extern "C" void kernel_launch(void* const* d_in, const int* in_sizes, int n_in,
                              void* d_out, int out_size) {
    const int*   ei    = (const int*)d_in[0];     // [2, E]
    const int*   et    = (const int*)d_in[1];     // [E]
    const float* w1    = (const float*)d_in[2];   // [R, N, H]
    const float* root1 = (const float*)d_in[3];   // [N, H]
    const float* b1    = (const float*)d_in[4];   // [H]
    const float* w2    = (const float*)d_in[5];   // [R, H, C]
    const float* root2 = (const float*)d_in[6];   // [H, C]
    const float* b2    = (const float*)d_in[7];   // [C]
    float* out = (float*)d_out;

    const int E = in_sizes[0] / 2;
    const int* srcv = ei;
    const int* dstv = ei + E;

    const int T = 256;
    k_init_hist <<<(E + T - 1) / T, T>>> (et, dstv, out, E);
    k_scan      <<<1, RR>>> ();
    k_scatter   <<<(E + T - 1) / T, T>>> (et, srcv, dstv, E);
    int pairs = (E + 1) / 2;
    int l1threads = 4 * pairs > RN ? 4 * pairs : RN;
    k_l1        <<<(l1threads + T - 1) / T, T>>> (w1, E);
    k_relu      <<<(NN * HH / 4 + T - 1) / T, T>>> ((const float4*)root1, b1);
    k_l2        <<<1184, T>>> (w2, out, E);
    k_fin       <<<(NN + T - 1) / T, T>>> (root2, b2, out);
}

// round 16
// speedup vs baseline: 2.4814x; 1.0839x over previous
#include <cuda_runtime.h>
#include <cuda_fp16.h>
#include <math.h>

constexpr int NN = 50000;   // nodes
constexpr int HH = 16;      // hidden
constexpr int RR = 32;      // relations
constexpr int CC = 8;       // classes
constexpr int RN = RR * NN; // segments
constexpr int EMAX = 1600000;

// Scratch (device globals: no allocation allowed).
// g_cnt invariant: zero at kernel_launch entry (zero-init at load; re-zeroed by k_l1).
__device__ int                g_cnt[RN];     // edge counts per (rel,dst)
__device__ float              g_x[NN * HH];  // layer-1 node features (fp32)
__device__ __align__(16) __half g_xh[NN * HH]; // fp16 copy for layer-2 gather
__device__ __align__(16) unsigned long long g_pk[EMAX + 4]; // s | d<<16 | r<<32 | c<<40
__device__ int                g_hist[RR];    // relation histogram (re-zeroed by k_scan)
__device__ int                g_cursor[RR];  // scatter cursors

// ---------------------------------------------------------------------------
// 0) zero g_x/out + relation histogram + (rel,dst) segment counts (2 edges/thread)
__global__ void k_init_hist(const int* __restrict__ et, const int* __restrict__ dstv,
                            float* __restrict__ out, int E) {
    __shared__ int sh[RR];
    int t = threadIdx.x;
    if (t < RR) sh[t] = 0;
    __syncthreads();
    int i = blockIdx.x * blockDim.x + t;
    if (i < NN * HH) g_x[i] = 0.0f;
    if (i < NN * CC) out[i] = 0.0f;
    int e0 = 2 * i;
    if (e0 < E) {
        int2 rr2 = *(const int2*)(et + e0);
        int2 dd2 = *(const int2*)(dstv + e0);
        atomicAdd(&sh[rr2.x], 1);
        atomicAdd(&g_cnt[rr2.x * NN + dd2.x], 1);
        if (e0 + 1 < E) {
            atomicAdd(&sh[rr2.y], 1);
            atomicAdd(&g_cnt[rr2.y * NN + dd2.y], 1);
        }
    }
    __syncthreads();
    if (t < RR) {
        int v = sh[t];
        if (v) atomicAdd(&g_hist[t], v);
    }
}

// 1) exclusive scan of 32-bin histogram -> cursors; re-zero g_hist for next replay
__global__ void k_scan() {
    __shared__ int s[RR];
    int t = threadIdx.x;
    s[t] = g_hist[t];
    __syncthreads();
    if (t == 0) {
        int acc = 0;
        for (int i = 0; i < RR; i++) { int v = s[i]; s[i] = acc; acc += v; }
    }
    __syncthreads();
    g_cursor[t] = s[t];
    g_hist[t] = 0;
}

// 2) scatter edges into relation-sorted packed array (warp-aggregated ranks);
//    bakes the (final) segment count into the edge word.
__global__ void k_scatter(const int* __restrict__ et, const int* __restrict__ srcv,
                          const int* __restrict__ dstv, int E) {
    __shared__ int sh[RR];
    __shared__ int sbase[RR];
    int t = threadIdx.x;
    if (t < RR) sh[t] = 0;
    __syncthreads();

    int e = blockIdx.x * blockDim.x + t;
    bool ok = e < E;
    int r = ok ? et[e] : RR;
    int s = 0, d = 0;
    if (ok) { s = srcv[e]; d = dstv[e]; }

    unsigned m = __match_any_sync(0xffffffffu, r);
    int lane = t & 31;
    int leader = __ffs(m) - 1;
    int pre = __popc(m & ((1u << lane) - 1));
    int base = 0;
    if (lane == leader && r < RR) base = atomicAdd(&sh[r], __popc(m));
    base = __shfl_sync(0xffffffffu, base, leader);
    int rank = base + pre;

    __syncthreads();
    if (t < RR) sbase[t] = sh[t] ? atomicAdd(&g_cursor[t], sh[t]) : 0;
    __syncthreads();

    if (ok) {
        unsigned c = (unsigned)__ldg(&g_cnt[r * NN + d]);   // final count
        g_pk[sbase[r] + rank] = (unsigned long long)(unsigned)s
                              | ((unsigned long long)(unsigned)d << 16)
                              | ((unsigned long long)(unsigned)r << 32)
                              | ((unsigned long long)c << 40);
    }
}

// 3) layer-1 scatter: x[d] += (1/c) * w1[r,s]
//    4 edges per 4-lane group; lane q handles the q-th float4 of each edge.
//    Also re-zeroes g_cnt (coalesced; restores the replay invariant).
__global__ void k_l1(const float* __restrict__ w1, int E) {
    int idx = blockIdx.x * blockDim.x + threadIdx.x;
    if (idx < RN) g_cnt[idx] = 0;                 // fold re-zeroing into this pass

    int g = idx >> 2, q = idx & 3;
    int e0 = 4 * g;
    if (e0 >= E) return;

    const ulonglong2* pk2 = (const ulonglong2*)g_pk;
    ulonglong2 pa = __ldg(pk2 + 2 * g);
    ulonglong2 pb = __ldg(pk2 + 2 * g + 1);
    unsigned long long pp[4] = {pa.x, pa.y, pb.x, pb.y};

    int  sv[4], dv[4], rv[4], cv[4];
#pragma unroll
    for (int k = 0; k < 4; k++) {
        sv[k] = (int)(pp[k] & 0xFFFFu);
        dv[k] = (int)((pp[k] >> 16) & 0xFFFFu);
        rv[k] = (int)((pp[k] >> 32) & 0xFFu);
        cv[k] = (int)((pp[k] >> 40) & 0xFFFFu);
    }

    // issue all gathers first (max MLP)
    float4 w[4];
#pragma unroll
    for (int k = 0; k < 4; k++)
        w[k] = __ldg(((const float4*)(w1 + ((long)(rv[k] * NN + sv[k]) << 4))) + q);

#pragma unroll
    for (int k = 0; k < 4; k++) {
        if (e0 + k < E) {
            float inv = __fdividef(1.0f, (float)(cv[k] > 0 ? cv[k] : 1));
            float* pd = &g_x[dv[k] * HH + q * 4];
            asm volatile("red.global.add.v4.f32 [%0], {%1,%2,%3,%4};"
                         :: "l"(pd), "f"(w[k].x * inv), "f"(w[k].y * inv),
                            "f"(w[k].z * inv), "f"(w[k].w * inv) : "memory");
        }
    }
}

// 4) x = relu(x + root1 + b1)  (float4); also writes fp16 copy for l2 gather
__global__ void k_relu(const float4* __restrict__ root1, const float* __restrict__ b1) {
    int i = blockIdx.x * blockDim.x + threadIdx.x;
    if (i >= NN * HH / 4) return;
    float4 v = ((float4*)g_x)[i];
    float4 rr = __ldg(root1 + i);
    int q = (i & 3) * 4;
    v.x += rr.x + b1[q];
    v.y += rr.y + b1[q + 1];
    v.z += rr.z + b1[q + 2];
    v.w += rr.w + b1[q + 3];
    v.x = fmaxf(v.x, 0.f); v.y = fmaxf(v.y, 0.f);
    v.z = fmaxf(v.z, 0.f); v.w = fmaxf(v.w, 0.f);
    ((float4*)g_x)[i] = v;
    __half2 h0 = __floats2half2_rn(v.x, v.y);
    __half2 h1 = __floats2half2_rn(v.z, v.w);
    ((__half2*)g_xh)[2 * i]     = h0;
    ((__half2*)g_xh)[2 * i + 1] = h1;
}

// 5) layer-2 scatter: out[d] += (1/c) * (x[s] @ w2[r])
//    2 edges per thread (ulonglong2 pk + 4 fp16 x loads in flight); fp32 math.
__global__ void __launch_bounds__(256) k_l2(const float* __restrict__ w2,
                                            float* __restrict__ out, int E) {
    __shared__ float s_w2[RR * HH * CC];   // 16 KB
    for (int i = threadIdx.x; i < RR * HH * CC; i += blockDim.x) s_w2[i] = w2[i];
    __syncthreads();

    int P = (E + 1) >> 1;
    int stride = gridDim.x * blockDim.x;
    const ulonglong2* pk2 = (const ulonglong2*)g_pk;

    for (int g = blockIdx.x * blockDim.x + threadIdx.x; g < P; g += stride) {
        ulonglong2 pv = __ldg(pk2 + g);
        bool ok1 = (2 * g + 1) < E;

        int s0 = (int)(pv.x & 0xFFFFu), d0 = (int)((pv.x >> 16) & 0xFFFFu);
        int r0 = (int)((pv.x >> 32) & 0xFFu), c0 = (int)((pv.x >> 40) & 0xFFFFu);
        int s1 = (int)(pv.y & 0xFFFFu), d1 = (int)((pv.y >> 16) & 0xFFFFu);
        int r1 = (int)((pv.y >> 32) & 0xFFu), c1 = (int)((pv.y >> 40) & 0xFFFFu);
        if (!ok1) { s1 = s0; r1 = r0; }

        const uint4* xr0 = (const uint4*)(g_xh + s0 * HH);
        const uint4* xr1 = (const uint4*)(g_xh + s1 * HH);
        uint4 hA0 = __ldg(xr0), hB0 = __ldg(xr0 + 1);
        uint4 hA1 = __ldg(xr1), hB1 = __ldg(xr1 + 1);

        float i0 = __fdividef(1.0f, (float)(c0 > 0 ? c0 : 1));
        float i1 = __fdividef(1.0f, (float)(c1 > 0 ? c1 : 1));

        const float* wr0 = s_w2 + r0 * HH * CC;
        const float* wr1 = s_w2 + r1 * HH * CC;

        float y0[CC] = {0,0,0,0,0,0,0,0};
        float y1[CC] = {0,0,0,0,0,0,0,0};
        {
            const unsigned* ha0 = (const unsigned*)&hA0;
            const unsigned* hb0 = (const unsigned*)&hB0;
            const unsigned* ha1 = (const unsigned*)&hA1;
            const unsigned* hb1 = (const unsigned*)&hB1;
#pragma unroll
            for (int hp = 0; hp < 8; hp++) {
                unsigned u0 = (hp < 4) ? ha0[hp] : hb0[hp - 4];
                unsigned u1 = (hp < 4) ? ha1[hp] : hb1[hp - 4];
                float2 f0 = __half22float2(*(const __half2*)&u0);
                float2 f1 = __half22float2(*(const __half2*)&u1);
                const float* wa = wr0 + (2 * hp) * CC;
                const float* wb = wr1 + (2 * hp) * CC;
#pragma unroll
                for (int c = 0; c < CC; c++) {
                    y0[c] += f0.x * wa[c] + f0.y * wa[CC + c];
                    y1[c] += f1.x * wb[c] + f1.y * wb[CC + c];
                }
            }
        }

        float* pd0 = out + d0 * CC;
        asm volatile("red.global.add.v4.f32 [%0], {%1,%2,%3,%4};"
                     :: "l"(pd0), "f"(y0[0] * i0), "f"(y0[1] * i0),
                        "f"(y0[2] * i0), "f"(y0[3] * i0) : "memory");
        asm volatile("red.global.add.v4.f32 [%0], {%1,%2,%3,%4};"
                     :: "l"(pd0 + 4), "f"(y0[4] * i0), "f"(y0[5] * i0),
                        "f"(y0[6] * i0), "f"(y0[7] * i0) : "memory");
        if (ok1) {
            float* pd1 = out + d1 * CC;
            asm volatile("red.global.add.v4.f32 [%0], {%1,%2,%3,%4};"
                         :: "l"(pd1), "f"(y1[0] * i1), "f"(y1[1] * i1),
                            "f"(y1[2] * i1), "f"(y1[3] * i1) : "memory");
            asm volatile("red.global.add.v4.f32 [%0], {%1,%2,%3,%4};"
                         :: "l"(pd1 + 4), "f"(y1[4] * i1), "f"(y1[5] * i1),
                            "f"(y1[6] * i1), "f"(y1[7] * i1) : "memory");
        }
    }
}

// 6) finalize: out = log_softmax(out + x @ root2 + b2)   (fp32 x)
__global__ void k_fin(const float* __restrict__ root2, const float* __restrict__ b2,
                      float* __restrict__ out) {
    __shared__ float s_r2[HH * CC];
    __shared__ float s_b2[CC];
    for (int i = threadIdx.x; i < HH * CC; i += blockDim.x) s_r2[i] = root2[i];
    if (threadIdx.x < CC) s_b2[threadIdx.x] = b2[threadIdx.x];
    __syncthreads();

    int n = blockIdx.x * blockDim.x + threadIdx.x;
    if (n >= NN) return;

    float y[CC];
    float4 a0 = *(const float4*)(out + n * CC);
    float4 a1 = *(const float4*)(out + n * CC + 4);
    y[0] = a0.x; y[1] = a0.y; y[2] = a0.z; y[3] = a0.w;
    y[4] = a1.x; y[5] = a1.y; y[6] = a1.z; y[7] = a1.w;

#pragma unroll
    for (int h = 0; h < HH; h++) {
        float xv = g_x[n * HH + h];
#pragma unroll
        for (int c = 0; c < CC; c++) y[c] += xv * s_r2[h * CC + c];
    }
#pragma unroll
    for (int c = 0; c < CC; c++) y[c] += s_b2[c];

    float m = y[0];
#pragma unroll
    for (int c = 1; c < CC; c++) m = fmaxf(m, y[c]);
    float sum = 0.0f;
#pragma unroll
    for (int c = 0; c < CC; c++) sum += __expf(y[c] - m);
    float l = m + logf(sum);
#pragma unroll
    for (int c = 0; c < CC; c++) out[n * CC + c] = y[c] - l;
}

// ---------------------------------------------------------------------------
extern "C" void kernel_launch(void* const* d_in, const int* in_sizes, int n_in,
                              void* d_out, int out_size) {
    const int*   ei    = (const int*)d_in[0];     // [2, E]
    const int*   et    = (const int*)d_in[1];     // [E]
    const float* w1    = (const float*)d_in[2];   // [R, N, H]
    const float* root1 = (const float*)d_in[3];   // [N, H]
    const float* b1    = (const float*)d_in[4];   // [H]
    const float* w2    = (const float*)d_in[5];   // [R, H, C]
    const float* root2 = (const float*)d_in[6];   // [H, C]
    const float* b2    = (const float*)d_in[7];   // [C]
    float* out = (float*)d_out;

    const int E = in_sizes[0] / 2;
    const int* srcv = ei;
    const int* dstv = ei + E;

    const int T = 256;
    k_init_hist <<<(NN * HH + T - 1) / T, T>>> (et, dstv, out, E);   // covers 2*threads >= E edges
    k_scan      <<<1, RR>>> ();
    k_scatter   <<<(E + T - 1) / T, T>>> (et, srcv, dstv, E);
    int l1threads = E > RN ? E : RN;                                  // 4 edges per 4-lane group
    k_l1        <<<(l1threads + T - 1) / T, T>>> (w1, E);
    k_relu      <<<(NN * HH / 4 + T - 1) / T, T>>> ((const float4*)root1, b1);
    k_l2        <<<1184, T>>> (w2, out, E);
    k_fin       <<<(NN + T - 1) / T, T>>> (root2, b2, out);
}